// round 1
// baseline (speedup 1.0000x reference)
#include <cuda_runtime.h>
#include <cuda_bf16.h>

// RoIAlign1D: feat [B,T,D] f32, spans [B,K,2] i32, lengths [B] i32 -> out [B,K,P,D] f32
// P = 16 (fixed by problem). D = 512 -> 128 float4 per row.
//
// One block per (b,k,p) sample; 128 threads; thread d4 moves float4 #d4 of the
// 512-float row. Span math computed redundantly per-thread (cheap ALU).

#define P_SAMPLES 16

__global__ void __launch_bounds__(128) roialign1d_kernel(
    const float4* __restrict__ feat,   // [B, T, D/4]
    const int*    __restrict__ spans,  // [B, K, 2]
    const int*    __restrict__ lengths,// [B]
    float4*       __restrict__ out,    // [B, K, P, D/4]
    int K, int T, int D4)
{
    const int sidx = blockIdx.x;                 // b*K*P + k*P + p
    const int p   = sidx & (P_SAMPLES - 1);
    const int bk  = sidx >> 4;                   // b*K + k
    const int b   = bk / K;

    // ---- span math (uniform across the block) ----
    const int Lm1 = lengths[b] - 1;
    int a0 = spans[bk * 2 + 0];
    int a1 = spans[bk * 2 + 1];
    a0 = min(max(a0, 0), Lm1);
    a1 = min(max(a1, 0), Lm1);
    const int s = min(a0, a1);
    const int e = max(a0, a1);
    const int segm1 = e - s;                     // seglen - 1

    const float t   = (float)p * (1.0f / (P_SAMPLES - 1)) * 0.0f
                    + (float)p / (float)(P_SAMPLES - 1);   // p/15.0f (match jax f32 div)
    const float idx = t * (float)segm1;
    int i0 = (int)floorf(idx);
    i0 = min(i0, segm1);
    const int i1 = min(i0 + 1, segm1);
    const float w = idx - (float)i0;

    const long long row0 = (long long)(b * T + s + i0) * D4;
    const long long row1 = (long long)(b * T + s + i1) * D4;
    const long long orow = (long long)sidx * D4;

    const int d4 = threadIdx.x;                  // 0..127
    const float4 f0 = feat[row0 + d4];
    const float4 f1 = feat[row1 + d4];
    float4 r;
    const float wm = 1.0f - w;
    r.x = wm * f0.x + w * f1.x;
    r.y = wm * f0.y + w * f1.y;
    r.z = wm * f0.z + w * f1.z;
    r.w = wm * f0.w + w * f1.w;
    out[orow + d4] = r;
}

extern "C" void kernel_launch(void* const* d_in, const int* in_sizes, int n_in,
                              void* d_out, int out_size)
{
    const float* feat    = (const float*)d_in[0];
    const int*   spans   = (const int*)d_in[1];
    const int*   lengths = (const int*)d_in[2];
    float*       out     = (float*)d_out;

    const int B  = in_sizes[2];                      // 16
    const int K  = in_sizes[1] / (2 * B);            // 64
    const int TD = in_sizes[0] / B;                  // T*D
    const int D  = out_size / (B * K * P_SAMPLES);   // 512
    const int T  = TD / D;                           // 4096
    const int D4 = D / 4;                            // 128

    const int nblocks = B * K * P_SAMPLES;           // 16384
    roialign1d_kernel<<<nblocks, 128>>>(
        (const float4*)feat, spans, lengths, (float4*)out, K, T, D4);
}